// round 4
// baseline (speedup 1.0000x reference)
#include <cuda_runtime.h>
#include <cstdint>

// SNN: x[B,5] -> L1(32) -> spike(dot>=2) -> L2/L3/L4 (provably zero unless
// popc(mask1) >= g_minpop). Layer 1 in packed f32x2, two rows per lane-pair.

__device__ unsigned long long g_w1d[160];  // [(q*5+k)*4+r] = dup(W1[4q+r][k])
__device__ int g_minpop;

__global__ void setup_kernel(const float* __restrict__ W1,
                             const float* __restrict__ W2)
{
    int t = threadIdx.x;
    if (t < 160) {
        int r = t & 3;
        int qk = t >> 2;           // q*5+k
        int q = qk / 5, k = qk % 5;
        unsigned u = __float_as_uint(W1[(4 * q + r) * 5 + k]);
        g_w1d[t] = ((unsigned long long)u << 32) | (unsigned long long)u;
    }
    if (t >= 160 && t < 192) {     // one full warp
        int i = t - 160;
        float mx = W2[i];
        #pragma unroll
        for (int j = 1; j < 32; j++) mx = fmaxf(mx, W2[j * 32 + i]);
        #pragma unroll
        for (int s = 16; s > 0; s >>= 1)
            mx = fmaxf(mx, __shfl_xor_sync(0xffffffffu, mx, s));
        if (i == 0) {
            int mp = 1;  // smallest count whose bound could reach 2 (conservative)
            while (mp < 33 && (float)mp * mx < 1.99f) mp++;
            g_minpop = mp;
        }
    }
}

__device__ __forceinline__ unsigned long long fma2(unsigned long long a,
                                                   unsigned long long b,
                                                   unsigned long long c) {
    unsigned long long d;
    asm("fma.rn.f32x2 %0, %1, %2, %3;" : "=l"(d) : "l"(a), "l"(b), "l"(c));
    return d;
}
__device__ __forceinline__ unsigned long long mul2(unsigned long long a,
                                                   unsigned long long b) {
    unsigned long long d;
    asm("mul.rn.f32x2 %0, %1, %2;" : "=l"(d) : "l"(a), "l"(b));
    return d;
}
__device__ __forceinline__ unsigned long long add2(unsigned long long a,
                                                   unsigned long long b) {
    unsigned long long d;
    asm("add.rn.f32x2 %0, %1, %2;" : "=l"(d) : "l"(a), "l"(b));
    return d;
}
__device__ __forceinline__ unsigned long long pk2(float lo, float hi) {
    unsigned long long r;
    asm("mov.b64 %0, {%1,%2};" : "=l"(r) : "f"(lo), "f"(hi));
    return r;
}

// exact layers 2-4 (rare, ~1e-3 of rows); validated rel_err==0 in R1-R3.
__device__ __noinline__ unsigned rare_path(unsigned mask1,
                                           const float* __restrict__ W2,
                                           const float* __restrict__ W3,
                                           const float* __restrict__ W4)
{
    unsigned mask2 = 0;
    #pragma unroll
    for (int jc = 0; jc < 32; jc += 8) {
        float acc[8] = {0, 0, 0, 0, 0, 0, 0, 0};
        unsigned mm = mask1;
        while (mm) {
            int i = __ffs(mm) - 1; mm &= mm - 1;
            #pragma unroll
            for (int j = 0; j < 8; j++) acc[j] += W2[(jc + j) * 32 + i];
        }
        #pragma unroll
        for (int j = 0; j < 8; j++)
            if (acc[j] >= 2.0f) mask2 |= 1u << (jc + j);
    }
    if (!mask2) return 0;

    unsigned mask3 = 0;
    #pragma unroll
    for (int jc = 0; jc < 16; jc += 8) {
        float acc[8] = {0, 0, 0, 0, 0, 0, 0, 0};
        unsigned mm = mask2;
        while (mm) {
            int i = __ffs(mm) - 1; mm &= mm - 1;
            #pragma unroll
            for (int j = 0; j < 8; j++) acc[j] += W3[(jc + j) * 32 + i];
        }
        #pragma unroll
        for (int j = 0; j < 8; j++)
            if (acc[j] >= 2.0f) mask3 |= 1u << (jc + j);
    }
    if (!mask3) return 0;

    float acc4[10];
    #pragma unroll
    for (int j = 0; j < 10; j++) acc4[j] = 0.0f;
    unsigned mm = mask3;
    while (mm) {
        int i = __ffs(mm) - 1; mm &= mm - 1;
        #pragma unroll
        for (int j = 0; j < 10; j++) acc4[j] += W4[j * 16 + i];
    }
    unsigned om = 0;
    #pragma unroll
    for (int j = 0; j < 10; j++)
        if (acc4[j] >= 2.0f) om |= 1u << j;
    return om;
}

#define BT  256
#define RPT 4
#define RPB (BT * RPT)   // 1024 rows per block

__global__ __launch_bounds__(BT)
void snn_kernel(const float* __restrict__ x,
                const float* __restrict__ W2,
                const float* __restrict__ W3,
                const float* __restrict__ W4,
                float* __restrict__ out)
{
    __shared__ unsigned long long sW[160];   // duplicated W1, 1280B

    const int tid = threadIdx.x;
    const size_t rowbase = (size_t)blockIdx.x * RPB;
    const int mp = g_minpop;

    if (tid < 80)
        reinterpret_cast<float4*>(sW)[tid] =
            reinterpret_cast<const float4*>(g_w1d)[tid];

    // zero-fill this block's output tile (coalesced STG.128); rare scatter
    // after __syncthreads overwrites the handful of nonzero rows.
    {
        float4* ov = reinterpret_cast<float4*>(out + rowbase * 10);
        const float4 z = make_float4(0.f, 0.f, 0.f, 0.f);
        #pragma unroll
        for (int i = tid; i < RPB * 10 / 4; i += BT) ov[i] = z;
    }
    __syncthreads();

    // load x for 4 rows (coalesced LDG.32), pack row-pairs into f32x2 lanes
    unsigned long long xp[2][5];
    {
        float xs[4][5];
        #pragma unroll
        for (int s = 0; s < 4; s++) {
            const float* xr = x + (rowbase + (size_t)tid + 256u * s) * 5;
            #pragma unroll
            for (int k = 0; k < 5; k++) xs[s][k] = __ldg(xr + k);
        }
        #pragma unroll
        for (int k = 0; k < 5; k++) {
            xp[0][k] = pk2(xs[0][k], xs[1][k]);
            xp[1][k] = pk2(xs[2][k], xs[3][k]);
        }
    }

    uint32_t swa;
    asm("{ .reg .u64 t; cvta.to.shared.u64 t, %1; cvt.u32.u64 %0, t; }"
        : "=r"(swa) : "l"(sW));

    const unsigned long long M2 = 0xC0000000C0000000ULL;  // (-2, -2)

    unsigned mask[4] = {0, 0, 0, 0};   // one 32-bit layer-1 mask per row

    #pragma unroll
    for (int q = 0; q < 8; q++) {
        unsigned long long acc[2][4];
        #pragma unroll
        for (int k = 0; k < 5; k++) {
            unsigned long long wa, wb, wc, wd;
            unsigned off = (unsigned)(((q * 5 + k) * 4) * 8);
            asm("ld.shared.v2.u64 {%0,%1}, [%2];"
                : "=l"(wa), "=l"(wb) : "r"(swa + off));
            asm("ld.shared.v2.u64 {%0,%1}, [%2];"
                : "=l"(wc), "=l"(wd) : "r"(swa + off + 16));
            if (k == 0) {
                #pragma unroll
                for (int p = 0; p < 2; p++) {
                    acc[p][0] = mul2(wa, xp[p][0]);
                    acc[p][1] = mul2(wb, xp[p][0]);
                    acc[p][2] = mul2(wc, xp[p][0]);
                    acc[p][3] = mul2(wd, xp[p][0]);
                }
            } else {
                #pragma unroll
                for (int p = 0; p < 2; p++) {
                    acc[p][0] = fma2(wa, xp[p][k], acc[p][0]);
                    acc[p][1] = fma2(wb, xp[p][k], acc[p][1]);
                    acc[p][2] = fma2(wc, xp[p][k], acc[p][2]);
                    acc[p][3] = fma2(wd, xp[p][k], acc[p][3]);
                }
            }
        }
        // spike test: sign(a-2)==0  <=>  a >= 2   (exact; add of -2 == sub 2)
        #pragma unroll
        for (int p = 0; p < 2; p++) {
            #pragma unroll
            for (int r = 0; r < 4; r++) {
                unsigned long long d = add2(acc[p][r], M2);
                unsigned lo = (unsigned)d;
                unsigned hi = (unsigned)(d >> 32);
                int j = 4 * q + r;
                mask[2 * p + 0] |= (~(lo >> (31 - j))) & (1u << j);
                mask[2 * p + 1] |= (~(hi >> (31 - j))) & (1u << j);
            }
        }
    }

    unsigned om[4];
    #pragma unroll
    for (int s = 0; s < 4; s++)
        om[s] = (__popc(mask[s]) >= mp) ? rare_path(mask[s], W2, W3, W4) : 0u;

    __syncthreads();   // order zero-fill before rare scatter (CTA fence)

    #pragma unroll
    for (int s = 0; s < 4; s++) {
        if (om[s]) {
            float* o = out + (rowbase + (size_t)tid + 256u * s) * 10;
            #pragma unroll
            for (int j = 0; j < 10; j++)
                o[j] = ((om[s] >> j) & 1u) ? 1.0f : 0.0f;
        }
    }
}

extern "C" void kernel_launch(void* const* d_in, const int* in_sizes, int n_in,
                              void* d_out, int out_size)
{
    const float* x  = (const float*)d_in[0];
    const float* W1 = (const float*)d_in[1];
    const float* W2 = (const float*)d_in[2];
    const float* W3 = (const float*)d_in[3];
    const float* W4 = (const float*)d_in[4];
    float* out = (float*)d_out;

    const int B = in_sizes[0] / 5;        // 2097152
    const int grid = B / RPB;             // 2048

    setup_kernel<<<1, 192>>>(W1, W2);
    snn_kernel<<<grid, BT>>>(x, W2, W3, W4, out);
}

// round 5
// speedup vs baseline: 1.1650x; 1.1650x over previous
#include <cuda_runtime.h>
#include <cstdint>

// SNN: x[B,5] -> L1(32) -> spike(dot>=2) -> L2(32) -> L3(16) -> L4(10) -> spike.
// Layer 1 exact scalar FFMA, 2 rows/thread sharing LDS.128 weight broadcasts.
// Layers 2-4 provably all-zero unless popc(mask1) >= g_minpop (sound bound via
// max column-max of W2); rare exact path (~1e-3 of rows) reads W2/W3/W4 from L2.

__device__ int g_minpop;

__global__ void setup_kernel(const float* __restrict__ W2) {
    int i = threadIdx.x;
    float mx = W2[i];
    #pragma unroll
    for (int j = 1; j < 32; j++) mx = fmaxf(mx, W2[j * 32 + i]);
    #pragma unroll
    for (int s = 16; s > 0; s >>= 1)
        mx = fmaxf(mx, __shfl_xor_sync(0xffffffffu, mx, s));
    if (i == 0) {
        int mp = 1;  // smallest popc whose bound popc*cmax could round to >= 2
        while (mp < 33 && (float)mp * mx < 1.99f) mp++;
        g_minpop = mp;
    }
}

// exact layers 2-4 (rare); identical to R1-R4 validated code (rel_err == 0).
__device__ __noinline__ unsigned rare_path(unsigned mask1,
                                           const float* __restrict__ W2,
                                           const float* __restrict__ W3,
                                           const float* __restrict__ W4)
{
    unsigned mask2 = 0;
    #pragma unroll
    for (int jc = 0; jc < 32; jc += 8) {
        float acc[8] = {0, 0, 0, 0, 0, 0, 0, 0};
        unsigned mm = mask1;
        while (mm) {
            int i = __ffs(mm) - 1; mm &= mm - 1;
            #pragma unroll
            for (int j = 0; j < 8; j++) acc[j] += W2[(jc + j) * 32 + i];
        }
        #pragma unroll
        for (int j = 0; j < 8; j++)
            if (acc[j] >= 2.0f) mask2 |= 1u << (jc + j);
    }
    if (!mask2) return 0;

    unsigned mask3 = 0;
    #pragma unroll
    for (int jc = 0; jc < 16; jc += 8) {
        float acc[8] = {0, 0, 0, 0, 0, 0, 0, 0};
        unsigned mm = mask2;
        while (mm) {
            int i = __ffs(mm) - 1; mm &= mm - 1;
            #pragma unroll
            for (int j = 0; j < 8; j++) acc[j] += W3[(jc + j) * 32 + i];
        }
        #pragma unroll
        for (int j = 0; j < 8; j++)
            if (acc[j] >= 2.0f) mask3 |= 1u << (jc + j);
    }
    if (!mask3) return 0;

    float acc4[10];
    #pragma unroll
    for (int j = 0; j < 10; j++) acc4[j] = 0.0f;
    unsigned mm = mask3;
    while (mm) {
        int i = __ffs(mm) - 1; mm &= mm - 1;
        #pragma unroll
        for (int j = 0; j < 10; j++) acc4[j] += W4[j * 16 + i];
    }
    unsigned om = 0;
    #pragma unroll
    for (int j = 0; j < 10; j++)
        if (acc4[j] >= 2.0f) om |= 1u << j;
    return om;
}

#define BT  256
#define RPB 512   // 2 rows per thread

__global__ __launch_bounds__(BT)
void snn_kernel(const float* __restrict__ x,
                const float* __restrict__ W1,
                const float* __restrict__ W2,
                const float* __restrict__ W3,
                const float* __restrict__ W4,
                float* __restrict__ out)
{
    __shared__ float sW1[160];          // raw W1, read as float4 chunks
    __shared__ float sX[RPB * 5];       // 2560 floats

    const int tid = threadIdx.x;
    const size_t rowbase = (size_t)blockIdx.x * RPB;
    const int mp = g_minpop;

    if (tid < 40)
        reinterpret_cast<float4*>(sW1)[tid] =
            reinterpret_cast<const float4*>(W1)[tid];

    // stage x tile: 640 float4, coalesced
    {
        const float4* xv = reinterpret_cast<const float4*>(x) + rowbase * 5 / 4;
        float4* sx4 = reinterpret_cast<float4*>(sX);
        #pragma unroll
        for (int i = tid; i < RPB * 5 / 4; i += BT) sx4[i] = xv[i];
    }
    __syncthreads();

    // zero-fill this block's output tile (coalesced STG.128, fire-and-forget;
    // latency hides under the FMA block below). Rare scatter after the second
    // __syncthreads (CTA-scope ordering) overwrites the few nonzero rows.
    {
        float4* ov = reinterpret_cast<float4*>(out + rowbase * 10);
        const float4 z = make_float4(0.f, 0.f, 0.f, 0.f);
        #pragma unroll
        for (int i = tid; i < RPB * 10 / 4; i += BT) ov[i] = z;
    }

    // two rows per thread: tid and tid+256 (LDS banks conflict-free: 5 coprime 32)
    float xa0 = sX[tid * 5 + 0], xa1 = sX[tid * 5 + 1], xa2 = sX[tid * 5 + 2],
          xa3 = sX[tid * 5 + 3], xa4 = sX[tid * 5 + 4];
    float xb0 = sX[(tid + 256) * 5 + 0], xb1 = sX[(tid + 256) * 5 + 1],
          xb2 = sX[(tid + 256) * 5 + 2], xb3 = sX[(tid + 256) * 5 + 3],
          xb4 = sX[(tid + 256) * 5 + 4];

    const float4* w4 = reinterpret_cast<const float4*>(sW1);
    unsigned mA = 0, mB = 0;

    #pragma unroll
    for (int c = 0; c < 8; c++) {   // 4 outputs per chunk, both rows
        float w[20];
        #pragma unroll
        for (int q = 0; q < 5; q++) {
            float4 t = w4[c * 5 + q];               // LDS.128 broadcast
            w[q * 4 + 0] = t.x; w[q * 4 + 1] = t.y;
            w[q * 4 + 2] = t.z; w[q * 4 + 3] = t.w;
        }
        #pragma unroll
        for (int r = 0; r < 4; r++) {
            // same mul->fma order as the reference-validated R2 kernel
            float a = w[r * 5 + 0] * xa0;
            float b = w[r * 5 + 0] * xb0;
            a = fmaf(w[r * 5 + 1], xa1, a);  b = fmaf(w[r * 5 + 1], xb1, b);
            a = fmaf(w[r * 5 + 2], xa2, a);  b = fmaf(w[r * 5 + 2], xb2, b);
            a = fmaf(w[r * 5 + 3], xa3, a);  b = fmaf(w[r * 5 + 3], xb3, b);
            a = fmaf(w[r * 5 + 4], xa4, a);  b = fmaf(w[r * 5 + 4], xb4, b);
            if (a >= 2.0f) mA |= 1u << (4 * c + r);
            if (b >= 2.0f) mB |= 1u << (4 * c + r);
        }
    }

    unsigned omA = (__popc(mA) >= mp) ? rare_path(mA, W2, W3, W4) : 0u;
    unsigned omB = (__popc(mB) >= mp) ? rare_path(mB, W2, W3, W4) : 0u;

    __syncthreads();   // order zero-fill STGs before rare scatter (CTA fence)

    if (omA) {
        float* o = out + (rowbase + tid) * 10;
        #pragma unroll
        for (int j = 0; j < 10; j++) o[j] = ((omA >> j) & 1u) ? 1.0f : 0.0f;
    }
    if (omB) {
        float* o = out + (rowbase + tid + 256) * 10;
        #pragma unroll
        for (int j = 0; j < 10; j++) o[j] = ((omB >> j) & 1u) ? 1.0f : 0.0f;
    }
}

extern "C" void kernel_launch(void* const* d_in, const int* in_sizes, int n_in,
                              void* d_out, int out_size)
{
    const float* x  = (const float*)d_in[0];
    const float* W1 = (const float*)d_in[1];
    const float* W2 = (const float*)d_in[2];
    const float* W3 = (const float*)d_in[3];
    const float* W4 = (const float*)d_in[4];
    float* out = (float*)d_out;

    const int B = in_sizes[0] / 5;        // 2097152
    const int grid = B / RPB;             // 4096

    setup_kernel<<<1, 32>>>(W2);
    snn_kernel<<<grid, BT>>>(x, W1, W2, W3, W4, out);
}